// round 6
// baseline (speedup 1.0000x reference)
#include <cuda_runtime.h>
#include <math.h>
#include <stdint.h>

#define NN    100000
#define NE    1600000
#define NG    64
#define CATC  128
#define NHEAD 4
#define OUTD  64
#define EPSN  1e-5f
#define SLOPE 0.2f
#define SCAN_B ((NN + 1023) / 1024)   // 98

// ---------------- scratch (device globals) ----------------
__device__ float g_bufX[NN * CATC];
__device__ float g_bufH[NN * CATC];
__device__ float g_ssrc[NN * NHEAD];
__device__ float g_sdst[NN * NHEAD];
__device__ float g_maxs[NHEAD];
__device__ float g_maxd[NHEAD];
__device__ float g_mean[NG * CATC];
__device__ float g_inv[NG * CATC];
__device__ float g_pool[NG * CATC];
__device__ int   g_start[NG + 2];
__device__ int   g_cnt[NN];
__device__ int   g_off[NN + 1];
__device__ int   g_cursor[NN];
__device__ int   g_bsum[SCAN_B];
__device__ int   g_boff[SCAN_B];
__device__ int   g_csr[NE];

__device__ __forceinline__ float lrelu(float x) { return x > 0.f ? x : SLOPE * x; }
__device__ __forceinline__ float eluf(float x)  { return x > 0.f ? x : __expf(x) - 1.f; }

__device__ __forceinline__ void atomicMaxF(float* a, float v) {
    if (v >= 0.f) atomicMax((int*)a, __float_as_int(v));
    else          atomicMin((unsigned int*)a, __float_as_uint(v));
}

__device__ __forceinline__ uint32_t tf32rn(float x) {
    uint32_t r;
    asm("cvt.rna.tf32.f32 %0, %1;" : "=r"(r) : "f"(x));
    return r;
}
__device__ __forceinline__ void mma8(float* d, uint32_t a0, uint32_t a1,
                                     uint32_t a2, uint32_t a3,
                                     uint32_t b0, uint32_t b1) {
    asm volatile(
        "mma.sync.aligned.m16n8k8.row.col.f32.tf32.tf32.f32 "
        "{%0,%1,%2,%3}, {%4,%5,%6,%7}, {%8,%9}, {%0,%1,%2,%3};"
        : "+f"(d[0]), "+f"(d[1]), "+f"(d[2]), "+f"(d[3])
        : "r"(a0), "r"(a1), "r"(a2), "r"(a3), "r"(b0), "r"(b1));
}

// ---------------- TF32 tensor GEMM: O[n,c]=sum_k A[n,k]*W[c,k] (+bias)(+scores) ---
// 256 thr = 8 warps (wm 0..3, wn 0..1). Warp: rows wm*32+mt*16, cols wn*64+nt*8.
// K chunks of 32 (kt 0..3). 3xTF32: d += aH*bH + aH*bL + aL*bH.
// smem floats: aF 8192 (mt,kt,lane: hi float4 + lo float4), bF 8192 (nt,kt,lane:
// {b0h,b1h,b0l,b1l}), + bias/asrc/adst.
#define TG_SMEM ((8192 + 8192 + 384) * 4)

template <int ASEL, int DSEL, bool BIAS, bool SCORES>
__global__ void __launch_bounds__(256, 2)
k_tgemm(const float* __restrict__ Aext,
        const float* __restrict__ W,
        const float* __restrict__ bias,
        const float* __restrict__ a_src,
        const float* __restrict__ a_dst) {
    extern __shared__ float sm[];
    float* aSm  = sm;            // 8192
    float* bSm  = sm + 8192;     // 8192
    float* sBia = sm + 16384;
    float* sSrc = sm + 16512;
    float* sDst = sm + 16640;

    const float* A = (ASEL == 0) ? Aext : g_bufX;
    float* O       = (DSEL == 0) ? g_bufX : g_bufH;

    int tid = threadIdx.x, wid = tid >> 5, lane = tid & 31;
    int wm = wid >> 1, wn = wid & 1, gid = lane >> 2, tig = lane & 3;
    int row0 = blockIdx.x * 128;

    if (tid < 128) {
        if (BIAS) sBia[tid] = bias[tid];
        if (SCORES) { sSrc[tid] = a_src[tid]; sDst[tid] = a_dst[tid]; }
    }

    float d[2][8][4];
#pragma unroll
    for (int mt = 0; mt < 2; mt++)
#pragma unroll
        for (int nt = 0; nt < 8; nt++)
#pragma unroll
            for (int f = 0; f < 4; f++) d[mt][nt][f] = 0.f;

    for (int ch = 0; ch < 4; ch++) {
        // stage A chunk -> fragment layout, hi/lo
#pragma unroll
        for (int i = 0; i < 4; i++) {
            int idx = tid * 4 + i;          // 0..1023
            int r = idx >> 3, q = idx & 7;
            int grow = row0 + r;
            float4 v = make_float4(0.f, 0.f, 0.f, 0.f);
            if (grow < NN) v = ((const float4*)A)[grow * 32 + ch * 8 + q];
            float e[4] = {v.x, v.y, v.z, v.w};
            int mt = r >> 4, rt = r & 15;
#pragma unroll
            for (int j = 0; j < 4; j++) {
                int c = q * 4 + j;
                int kt = c >> 3, ct = c & 7;
                int ln = (rt & 7) * 4 + (ct & 3);
                int slot = (rt >> 3) | ((ct >> 2) << 1);
                uint32_t hi = tf32rn(e[j]);
                uint32_t lo = tf32rn(e[j] - __uint_as_float(hi));
                int base = ((mt * 4 + kt) * 32 + ln) * 8;
                ((uint32_t*)aSm)[base + slot] = hi;
                ((uint32_t*)aSm)[base + 4 + slot] = lo;
            }
        }
        // stage W chunk -> fragment layout, hi/lo packed {b0h,b1h,b0l,b1l}
#pragma unroll
        for (int i = 0; i < 4; i++) {
            int idx = tid * 4 + i;
            int cO = idx >> 3, q = idx & 7;
            float4 v = ((const float4*)W)[cO * 32 + ch * 8 + q];
            float e[4] = {v.x, v.y, v.z, v.w};
            int nt = cO >> 3;
#pragma unroll
            for (int j = 0; j < 4; j++) {
                int k = q * 4 + j;
                int kt = k >> 3, ct = k & 7;
                int ln = (cO & 7) * 4 + (ct & 3);
                int sl = ct >> 2;
                uint32_t hi = tf32rn(e[j]);
                uint32_t lo = tf32rn(e[j] - __uint_as_float(hi));
                int base = ((nt * 4 + kt) * 32 + ln) * 4;
                ((uint32_t*)bSm)[base + sl] = hi;
                ((uint32_t*)bSm)[base + 2 + sl] = lo;
            }
        }
        __syncthreads();
#pragma unroll
        for (int kt = 0; kt < 4; kt++) {
            uint4 aH[2], aL[2];
#pragma unroll
            for (int mt = 0; mt < 2; mt++) {
                int base = (((wm * 2 + mt) * 4 + kt) * 32 + lane) * 2;
                aH[mt] = ((const uint4*)aSm)[base];
                aL[mt] = ((const uint4*)aSm)[base + 1];
            }
#pragma unroll
            for (int nt = 0; nt < 8; nt++) {
                uint4 b = ((const uint4*)bSm)[((wn * 8 + nt) * 4 + kt) * 32 + lane];
#pragma unroll
                for (int mt = 0; mt < 2; mt++) {
                    mma8(d[mt][nt], aH[mt].x, aH[mt].y, aH[mt].z, aH[mt].w, b.x, b.y);
                    mma8(d[mt][nt], aH[mt].x, aH[mt].y, aH[mt].z, aH[mt].w, b.z, b.w);
                    mma8(d[mt][nt], aL[mt].x, aL[mt].y, aL[mt].z, aL[mt].w, b.x, b.y);
                }
            }
        }
        __syncthreads();
    }

    // epilogue: store + fused scores
    float sc[2][2][2][2];  // [mt][rowhalf][headhalf][src/dst]
    if (SCORES) {
#pragma unroll
        for (int a = 0; a < 2; a++)
#pragma unroll
            for (int b = 0; b < 2; b++)
#pragma unroll
                for (int c = 0; c < 2; c++) {
                    sc[a][b][c][0] = 0.f; sc[a][b][c][1] = 0.f;
                }
    }
#pragma unroll
    for (int mt = 0; mt < 2; mt++) {
        int r0 = row0 + wm * 32 + mt * 16 + gid;
#pragma unroll
        for (int nt = 0; nt < 8; nt++) {
            int c0 = wn * 64 + nt * 8 + 2 * tig;
            float v0 = d[mt][nt][0], v1 = d[mt][nt][1];
            float v2 = d[mt][nt][2], v3 = d[mt][nt][3];
            if (SCORES) {
                int hh = nt >> 2;
                float s0 = sSrc[c0], s1 = sSrc[c0 + 1];
                float t0 = sDst[c0], t1 = sDst[c0 + 1];
                sc[mt][0][hh][0] += v0 * s0 + v1 * s1;
                sc[mt][0][hh][1] += v0 * t0 + v1 * t1;
                sc[mt][1][hh][0] += v2 * s0 + v3 * s1;
                sc[mt][1][hh][1] += v2 * t0 + v3 * t1;
            }
            if (BIAS) {
                float b0 = sBia[c0], b1 = sBia[c0 + 1];
                v0 += b0; v1 += b1; v2 += b0; v3 += b1;
            }
            if (r0 < NN) *(float2*)&O[r0 * CATC + c0] = make_float2(v0, v1);
            if (r0 + 8 < NN) *(float2*)&O[(r0 + 8) * CATC + c0] = make_float2(v2, v3);
        }
    }
    if (SCORES) {
#pragma unroll
        for (int a = 0; a < 2; a++)
#pragma unroll
            for (int b = 0; b < 2; b++)
#pragma unroll
                for (int c = 0; c < 2; c++)
#pragma unroll
                    for (int s = 0; s < 2; s++) {
                        float v = sc[a][b][c][s];
                        v += __shfl_xor_sync(0xffffffffu, v, 1);
                        v += __shfl_xor_sync(0xffffffffu, v, 2);
                        sc[a][b][c][s] = v;
                    }
        if (tig == 0) {
#pragma unroll
            for (int mt = 0; mt < 2; mt++)
#pragma unroll
                for (int rh = 0; rh < 2; rh++) {
                    int r = row0 + wm * 32 + mt * 16 + gid + rh * 8;
                    if (r < NN) {
#pragma unroll
                        for (int hh = 0; hh < 2; hh++) {
                            int head = wn * 2 + hh;
                            g_ssrc[r * 4 + head] = sc[mt][rh][hh][0];
                            g_sdst[r * 4 + head] = sc[mt][rh][hh][1];
                        }
                    }
                }
        }
    }
}

// ---------------- CSR build ----------------
__global__ void k_cnt_zero() {
    int i = blockIdx.x * blockDim.x + threadIdx.x;
    if (i < NN) g_cnt[i] = 0;
}
__global__ void k_deg(const int* __restrict__ ei) {
    int e = blockIdx.x * blockDim.x + threadIdx.x;
    if (e < NE) atomicAdd(&g_cnt[ei[NE + e]], 1);
}
__global__ void k_scan1() {
    __shared__ int wsum[8];
    int b = blockIdx.x, t = threadIdx.x;
    int idx0 = b * 1024 + t * 4;
    int v[4];
#pragma unroll
    for (int k = 0; k < 4; k++) v[k] = (idx0 + k < NN) ? g_cnt[idx0 + k] : 0;
    int s = v[0] + v[1] + v[2] + v[3];
    int lane = t & 31, wid = t >> 5;
    int incl = s;
#pragma unroll
    for (int off = 1; off <= 16; off <<= 1) {
        int nv = __shfl_up_sync(0xffffffffu, incl, off);
        if (lane >= off) incl += nv;
    }
    if (lane == 31) wsum[wid] = incl;
    __syncthreads();
    if (t == 0) {
        int r = 0;
#pragma unroll
        for (int w = 0; w < 8; w++) { int x = wsum[w]; wsum[w] = r; r += x; }
    }
    __syncthreads();
    int excl = incl - s + wsum[wid];
    int run = excl;
#pragma unroll
    for (int k = 0; k < 4; k++) {
        if (idx0 + k < NN) g_off[idx0 + k] = run;
        run += v[k];
    }
    if (t == 255) g_bsum[b] = excl + s;
}
__global__ void k_scan2() {
    int r = 0;
    for (int b = 0; b < SCAN_B; b++) { g_boff[b] = r; r += g_bsum[b]; }
    g_off[NN] = r;
}
__global__ void k_scan3() {
    int i = blockIdx.x * blockDim.x + threadIdx.x;
    if (i >= NN) return;
    int o = g_off[i] + g_boff[i >> 10];
    g_off[i] = o;
    g_cursor[i] = o;
}
__global__ void k_fill(const int* __restrict__ ei) {
    int e = blockIdx.x * blockDim.x + threadIdx.x;
    if (e >= NE) return;
    int dst = ei[NE + e];
    int pos = atomicAdd(&g_cursor[dst], 1);
    g_csr[pos] = ei[e];
}

// ---------------- per-head global max of scores ----------------
__global__ void k_shift_init() {
    if (threadIdx.x < NHEAD) {
        g_maxs[threadIdx.x] = __int_as_float(0xff800000u);
        g_maxd[threadIdx.x] = __int_as_float(0xff800000u);
    }
}
__global__ void k_shift() {
    int i0 = blockIdx.x * blockDim.x + threadIdx.x;
    int stride = gridDim.x * blockDim.x;
    float ms = __int_as_float(0xff800000u);
    float md = ms;
    for (int i = i0; i < NN * NHEAD; i += stride) {
        ms = fmaxf(ms, g_ssrc[i]);
        md = fmaxf(md, g_sdst[i]);
    }
#pragma unroll
    for (int off = 4; off <= 16; off <<= 1) {
        ms = fmaxf(ms, __shfl_xor_sync(0xffffffffu, ms, off));
        md = fmaxf(md, __shfl_xor_sync(0xffffffffu, md, off));
    }
    int lane = threadIdx.x & 31;
    if (lane < 4) {
        atomicMaxF(&g_maxs[lane], ms);
        atomicMaxF(&g_maxd[lane], md);
    }
}

// ---------------- fused GAT aggregate (warp per dst) ----------------
__global__ void k_gat(const float* __restrict__ bias) {
    int n = (blockIdx.x * blockDim.x + threadIdx.x) >> 5;
    if (n >= NN) return;
    int lane = threadIdx.x & 31;
    int head = lane >> 3;

    float shift = lrelu(g_maxs[head] + g_maxd[head]);
    float sd = g_sdst[n * 4 + head];

    float p = __expf(lrelu(g_ssrc[n * 4 + head] + sd) - shift);
    float4 hv = ((const float4*)g_bufH)[n * 32 + lane];
    float ax = hv.x * p, ay = hv.y * p, az = hv.z * p, aw = hv.w * p;
    float den = p;

    int o0 = g_off[n], o1 = g_off[n + 1];
    for (int base = o0; base < o1; base += 32) {
        int id = 0;
        if (base + lane < o1) id = g_csr[base + lane];
        int cnt = min(32, o1 - base);
#pragma unroll 4
        for (int j = 0; j < cnt; j++) {
            int src = __shfl_sync(0xffffffffu, id, j);
            float ss = g_ssrc[src * 4 + head];
            float pe = __expf(lrelu(ss + sd) - shift);
            float4 h = ((const float4*)g_bufH)[src * 32 + lane];
            ax += h.x * pe; ay += h.y * pe; az += h.z * pe; aw += h.w * pe;
            den += pe;
        }
    }
    float inv = 1.f / den;
    float4 b = ((const float4*)bias)[lane];
    float4 o;
    o.x = eluf(ax * inv + b.x);
    o.y = eluf(ay * inv + b.y);
    o.z = eluf(az * inv + b.z);
    o.w = eluf(aw * inv + b.w);
    ((float4*)g_bufX)[n * 32 + lane] = o;
}

// ---------------- graph segment offsets ----------------
__global__ void k_start_init() {
    int g = threadIdx.x;
    if (g <= NG) g_start[g] = NN;
}
__global__ void k_start_fill(const int* __restrict__ batch) {
    int i = blockIdx.x * blockDim.x + threadIdx.x;
    if (i >= NN) return;
    int b = batch[i];
    int bp = (i == 0) ? -1 : batch[i - 1];
    for (int g = bp + 1; g <= b; ++g) g_start[g] = i;
}

// ---------------- GraphNorm stats ----------------
__global__ void k_norm_stats(const float* __restrict__ nms) {
    __shared__ float sh[256], sh2[256];
    int g = blockIdx.x, q = blockIdx.y;
    int tc = threadIdx.x & 31, tr = threadIdx.x >> 5;
    int c = q * 32 + tc;
    int s0 = g_start[g], s1 = g_start[g + 1];
    float s = 0.f, s2 = 0.f;
    for (int r = s0 + tr; r < s1; r += 8) {
        float v = g_bufX[r * CATC + c];
        s += v; s2 += v * v;
    }
    sh[threadIdx.x] = s; sh2[threadIdx.x] = s2;
    __syncthreads();
    for (int off = 128; off >= 32; off >>= 1) {
        if (threadIdx.x < off) {
            sh[threadIdx.x] += sh[threadIdx.x + off];
            sh2[threadIdx.x] += sh2[threadIdx.x + off];
        }
        __syncthreads();
    }
    if (threadIdx.x < 32) {
        int cnt = s1 - s0;
        float mean = 0.f, inv = 0.f;
        if (cnt > 0) {
            float fc = (float)cnt;
            mean = sh[tc] / fc;
            float ms = nms[c];
            float var = sh2[tc] / fc - (2.f * ms - ms * ms) * mean * mean;
            inv = rsqrtf(var + EPSN);
        }
        g_mean[g * CATC + c] = mean;
        g_inv[g * CATC + c] = inv;
    }
}

__global__ void k_norm_apply(const int* __restrict__ batch,
                             const float* __restrict__ w, const float* __restrict__ b,
                             const float* __restrict__ nms) {
    int i = blockIdx.x * blockDim.x + threadIdx.x;
    if (i >= NN * 32) return;
    int n = i >> 5, c4 = i & 31;
    int g = batch[n];
    float4 v  = ((const float4*)g_bufX)[i];
    float4 mn = ((const float4*)g_mean)[g * 32 + c4];
    float4 iv = ((const float4*)g_inv)[g * 32 + c4];
    float4 wv = ((const float4*)w)[c4];
    float4 bv = ((const float4*)b)[c4];
    float4 mv = ((const float4*)nms)[c4];
    v.x = wv.x * (v.x - mv.x * mn.x) * iv.x + bv.x;
    v.y = wv.y * (v.y - mv.y * mn.y) * iv.y + bv.y;
    v.z = wv.z * (v.z - mv.z * mn.z) * iv.z + bv.z;
    v.w = wv.w * (v.w - mv.w * mn.w) * iv.w + bv.w;
    ((float4*)g_bufX)[i] = v;
}

// ---------------- global max pool ----------------
__global__ void k_pool() {
    __shared__ float sh[256];
    int g = blockIdx.x, q = blockIdx.y;
    int tc = threadIdx.x & 31, tr = threadIdx.x >> 5;
    int c = q * 32 + tc;
    int s0 = g_start[g], s1 = g_start[g + 1];
    float m = __int_as_float(0xff800000u);
    for (int r = s0 + tr; r < s1; r += 8)
        m = fmaxf(m, g_bufX[r * CATC + c]);
    sh[threadIdx.x] = m;
    __syncthreads();
    for (int off = 128; off >= 32; off >>= 1) {
        if (threadIdx.x < off) sh[threadIdx.x] = fmaxf(sh[threadIdx.x], sh[threadIdx.x + off]);
        __syncthreads();
    }
    if (threadIdx.x < 32) g_pool[g * CATC + c] = sh[tc];
}

// ---------------- final fc ----------------
__global__ void k_fc(const float* __restrict__ fw, const float* __restrict__ fb,
                     float* __restrict__ out) {
    int g = blockIdx.x, o = threadIdx.x;
    float acc = fb[o];
#pragma unroll
    for (int c = 0; c < CATC; c += 4) {
        float4 p  = *(const float4*)&g_pool[g * CATC + c];
        float4 wv = *(const float4*)&fw[o * CATC + c];
        acc += p.x * wv.x + p.y * wv.y + p.z * wv.z + p.w * wv.w;
    }
    out[g * OUTD + o] = acc;
}

// ---------------- launch ----------------
extern "C" void kernel_launch(void* const* d_in, const int* in_sizes, int n_in,
                              void* d_out, int out_size) {
    const float* x     = (const float*)d_in[0];
    const int*   ei    = (const int*)d_in[1];
    const int*   batch = (const int*)d_in[2];
    const float* enc_w = (const float*)d_in[3];
    const float* enc_b = (const float*)d_in[4];
    const float* w1    = (const float*)d_in[5];
    const float* as1   = (const float*)d_in[6];
    const float* ad1   = (const float*)d_in[7];
    const float* b1    = (const float*)d_in[8];
    const float* n1w   = (const float*)d_in[9];
    const float* n1b   = (const float*)d_in[10];
    const float* n1ms  = (const float*)d_in[11];
    const float* w2    = (const float*)d_in[12];
    const float* as2   = (const float*)d_in[13];
    const float* ad2   = (const float*)d_in[14];
    const float* b2    = (const float*)d_in[15];
    const float* n2w   = (const float*)d_in[16];
    const float* n2b   = (const float*)d_in[17];
    const float* n2ms  = (const float*)d_in[18];
    const float* fw    = (const float*)d_in[19];
    const float* fb    = (const float*)d_in[20];
    float* out = (float*)d_out;

    cudaFuncSetAttribute(k_tgemm<0, 0, true, false>,
                         cudaFuncAttributeMaxDynamicSharedMemorySize, TG_SMEM);
    cudaFuncSetAttribute(k_tgemm<1, 1, false, true>,
                         cudaFuncAttributeMaxDynamicSharedMemorySize, TG_SMEM);

    const int gemmBlocks = (NN + 127) / 128;
    const int elemBlocks = (NN * 32 + 255) / 256;
    const int gatBlocks  = (NN * 32 + 255) / 256;
    const int edgeBlocks = (NE + 255) / 256;

    k_start_init<<<1, NG + 1>>>();
    k_start_fill<<<(NN + 255) / 256, 256>>>(batch);
    k_cnt_zero<<<(NN + 255) / 256, 256>>>();
    k_deg<<<edgeBlocks, 256>>>(ei);
    k_scan1<<<SCAN_B, 256>>>();
    k_scan2<<<1, 1>>>();
    k_scan3<<<(NN + 255) / 256, 256>>>();
    k_fill<<<edgeBlocks, 256>>>(ei);

    // encoder
    k_tgemm<0, 0, true, false><<<gemmBlocks, 256, TG_SMEM>>>(x, enc_w, enc_b, nullptr, nullptr);

    // ---- layer 1 ----
    k_tgemm<1, 1, false, true><<<gemmBlocks, 256, TG_SMEM>>>(nullptr, w1, nullptr, as1, ad1);
    k_shift_init<<<1, 32>>>();
    k_shift<<<296, 256>>>();
    k_gat<<<gatBlocks, 256>>>(b1);
    k_norm_stats<<<dim3(NG, 4), 256>>>(n1ms);
    k_norm_apply<<<elemBlocks, 256>>>(batch, n1w, n1b, n1ms);

    // ---- layer 2 ----
    k_tgemm<1, 1, false, true><<<gemmBlocks, 256, TG_SMEM>>>(nullptr, w2, nullptr, as2, ad2);
    k_shift_init<<<1, 32>>>();
    k_shift<<<296, 256>>>();
    k_gat<<<gatBlocks, 256>>>(b2);
    k_norm_stats<<<dim3(NG, 4), 256>>>(n2ms);
    k_norm_apply<<<elemBlocks, 256>>>(batch, n2w, n2b, n2ms);

    // ---- pool + fc ----
    k_pool<<<dim3(NG, 4), 256>>>();
    k_fc<<<NG, OUTD>>>(fw, fb, out);
}

// round 7
// speedup vs baseline: 1.6086x; 1.6086x over previous
#include <cuda_runtime.h>
#include <math.h>
#include <stdint.h>

#define NN    100000
#define NE    1600000
#define NG    64
#define CATC  128
#define NHEAD 4
#define OUTD  64
#define EPSN  1e-5f
#define SLOPE 0.2f
#define SCAN_B ((NN + 1023) / 1024)   // 98

// ---------------- scratch (device globals) ----------------
__device__ float g_bufX[NN * CATC];
__device__ float g_bufH[NN * CATC];
__device__ float g_ssrc[NN * NHEAD];
__device__ float g_sdst[NN * NHEAD];
__device__ float g_maxs[NHEAD];
__device__ float g_maxd[NHEAD];
__device__ float g_mean[NG * CATC];
__device__ float g_inv[NG * CATC];
__device__ float g_pool[NG * CATC];
__device__ int   g_start[NG + 2];
__device__ int   g_cnt[NN];
__device__ int   g_off[NN + 1];
__device__ int   g_cursor[NN];
__device__ int   g_bsum[SCAN_B];
__device__ int   g_boff[SCAN_B];
__device__ int   g_csr[NE];
__device__ uint4 g_wfrag[16 * 16 * 32];   // [ntG][ktG][lane] {b0h,b1h,b0l,b1l}

__device__ __forceinline__ float lrelu(float x) { return x > 0.f ? x : SLOPE * x; }
__device__ __forceinline__ float eluf(float x)  { return x > 0.f ? x : __expf(x) - 1.f; }

__device__ __forceinline__ void atomicMaxF(float* a, float v) {
    if (v >= 0.f) atomicMax((int*)a, __float_as_int(v));
    else          atomicMin((unsigned int*)a, __float_as_uint(v));
}

__device__ __forceinline__ uint32_t tf32rn(float x) {
    uint32_t r;
    asm("cvt.rna.tf32.f32 %0, %1;" : "=r"(r) : "f"(x));
    return r;
}
__device__ __forceinline__ void mma8(float* d, uint32_t a0, uint32_t a1,
                                     uint32_t a2, uint32_t a3,
                                     uint32_t b0, uint32_t b1) {
    asm volatile(
        "mma.sync.aligned.m16n8k8.row.col.f32.tf32.tf32.f32 "
        "{%0,%1,%2,%3}, {%4,%5,%6,%7}, {%8,%9}, {%0,%1,%2,%3};"
        : "+f"(d[0]), "+f"(d[1]), "+f"(d[2]), "+f"(d[3])
        : "r"(a0), "r"(a1), "r"(a2), "r"(a3), "r"(b0), "r"(b1));
}

// ---------------- W -> fragment conversion (once per layer) ----------------
__global__ void k_wconv(const float* __restrict__ W) {
    int idx = blockIdx.x * blockDim.x + threadIdx.x;   // 8192
    if (idx >= 16 * 16 * 32) return;
    int lane = idx & 31, ktG = (idx >> 5) & 15, ntG = idx >> 9;
    int n = ntG * 8 + (lane >> 2);
    int k0 = ktG * 8 + (lane & 3);
    float v0 = W[n * CATC + k0];
    float v1 = W[n * CATC + k0 + 4];
    uint4 f;
    f.x = tf32rn(v0);
    f.y = tf32rn(v1);
    f.z = tf32rn(v0 - __uint_as_float(f.x));
    f.w = tf32rn(v1 - __uint_as_float(f.y));
    g_wfrag[idx] = f;
}

// ---------------- TF32 tensor GEMM: O[n,c]=sum_k A[n,k]*W[c,k] (+bias)(+scores) ---
// 256 thr = 8 warps (wm 0..3, wn 0..1). Raw A in smem [128][132]; B frags from
// g_wfrag via LDG. 3xTF32 in-register split.
#define TG_SMEM ((128 * 132 + 384) * 4)

template <int ASEL, int DSEL, bool BIAS, bool SCORES>
__global__ void __launch_bounds__(256, 2)
k_tgemm(const float* __restrict__ Aext,
        const float* __restrict__ bias,
        const float* __restrict__ a_src,
        const float* __restrict__ a_dst) {
    extern __shared__ float sm[];
    float* aT   = sm;                  // [128][132]
    float* sBia = sm + 128 * 132;
    float* sSrc = sBia + 128;
    float* sDst = sSrc + 128;

    const float* A = (ASEL == 0) ? Aext : g_bufX;
    float* O       = (DSEL == 0) ? g_bufX : g_bufH;

    int tid = threadIdx.x, wid = tid >> 5, lane = tid & 31;
    int wm = wid >> 1, wn = wid & 1, gid = lane >> 2, tig = lane & 3;
    int row0 = blockIdx.x * 128;

    if (tid < 128) {
        if (BIAS) sBia[tid] = bias[tid];
        if (SCORES) { sSrc[tid] = a_src[tid]; sDst[tid] = a_dst[tid]; }
    }

    // stage raw A tile (128 rows x 128 cols), padded stride 132
#pragma unroll
    for (int i = 0; i < 16; i++) {
        int idx = tid + 256 * i;       // 0..4095
        int r = idx >> 5, q = idx & 31;
        int grow = row0 + r;
        float4 v = make_float4(0.f, 0.f, 0.f, 0.f);
        if (grow < NN) v = ((const float4*)A)[grow * 32 + q];
        *(float4*)&aT[r * 132 + q * 4] = v;
    }
    __syncthreads();

    float d[2][8][4];
#pragma unroll
    for (int mt = 0; mt < 2; mt++)
#pragma unroll
        for (int nt = 0; nt < 8; nt++)
#pragma unroll
            for (int f = 0; f < 4; f++) d[mt][nt][f] = 0.f;

#pragma unroll 4
    for (int ktG = 0; ktG < 16; ktG++) {
        // B fragments for this kt (8 n-tiles)
        uint4 bb[8];
#pragma unroll
        for (int nt = 0; nt < 8; nt++)
            bb[nt] = g_wfrag[(((wn * 8 + nt) << 4) + ktG) * 32 + lane];
        // A fragments hi/lo (2 m-tiles)
        uint32_t aH[2][4], aL[2][4];
#pragma unroll
        for (int mt = 0; mt < 2; mt++) {
            int rb = wm * 32 + mt * 16 + gid;
            int c = ktG * 8 + tig;
            float v0 = aT[rb * 132 + c];
            float v1 = aT[(rb + 8) * 132 + c];
            float v2 = aT[rb * 132 + c + 4];
            float v3 = aT[(rb + 8) * 132 + c + 4];
            aH[mt][0] = tf32rn(v0); aL[mt][0] = tf32rn(v0 - __uint_as_float(aH[mt][0]));
            aH[mt][1] = tf32rn(v1); aL[mt][1] = tf32rn(v1 - __uint_as_float(aH[mt][1]));
            aH[mt][2] = tf32rn(v2); aL[mt][2] = tf32rn(v2 - __uint_as_float(aH[mt][2]));
            aH[mt][3] = tf32rn(v3); aL[mt][3] = tf32rn(v3 - __uint_as_float(aH[mt][3]));
        }
#pragma unroll
        for (int nt = 0; nt < 8; nt++)
#pragma unroll
            for (int mt = 0; mt < 2; mt++) {
                mma8(d[mt][nt], aH[mt][0], aH[mt][1], aH[mt][2], aH[mt][3], bb[nt].x, bb[nt].y);
                mma8(d[mt][nt], aH[mt][0], aH[mt][1], aH[mt][2], aH[mt][3], bb[nt].z, bb[nt].w);
                mma8(d[mt][nt], aL[mt][0], aL[mt][1], aL[mt][2], aL[mt][3], bb[nt].x, bb[nt].y);
            }
    }

    // epilogue: store + fused scores
    float sc[2][2][2][2];  // [mt][rowhalf][headhalf][src/dst]
    if (SCORES) {
#pragma unroll
        for (int a = 0; a < 2; a++)
#pragma unroll
            for (int b = 0; b < 2; b++)
#pragma unroll
                for (int c = 0; c < 2; c++) {
                    sc[a][b][c][0] = 0.f; sc[a][b][c][1] = 0.f;
                }
    }
#pragma unroll
    for (int mt = 0; mt < 2; mt++) {
        int r0 = row0 + wm * 32 + mt * 16 + gid;
#pragma unroll
        for (int nt = 0; nt < 8; nt++) {
            int c0 = wn * 64 + nt * 8 + 2 * tig;
            float v0 = d[mt][nt][0], v1 = d[mt][nt][1];
            float v2 = d[mt][nt][2], v3 = d[mt][nt][3];
            if (SCORES) {
                int hh = nt >> 2;
                float s0 = sSrc[c0], s1 = sSrc[c0 + 1];
                float t0 = sDst[c0], t1 = sDst[c0 + 1];
                sc[mt][0][hh][0] += v0 * s0 + v1 * s1;
                sc[mt][0][hh][1] += v0 * t0 + v1 * t1;
                sc[mt][1][hh][0] += v2 * s0 + v3 * s1;
                sc[mt][1][hh][1] += v2 * t0 + v3 * t1;
            }
            if (BIAS) {
                float b0 = sBia[c0], b1 = sBia[c0 + 1];
                v0 += b0; v1 += b1; v2 += b0; v3 += b1;
            }
            if (r0 < NN) *(float2*)&O[r0 * CATC + c0] = make_float2(v0, v1);
            if (r0 + 8 < NN) *(float2*)&O[(r0 + 8) * CATC + c0] = make_float2(v2, v3);
        }
    }
    if (SCORES) {
#pragma unroll
        for (int a = 0; a < 2; a++)
#pragma unroll
            for (int b = 0; b < 2; b++)
#pragma unroll
                for (int c = 0; c < 2; c++)
#pragma unroll
                    for (int s = 0; s < 2; s++) {
                        float v = sc[a][b][c][s];
                        v += __shfl_xor_sync(0xffffffffu, v, 1);
                        v += __shfl_xor_sync(0xffffffffu, v, 2);
                        sc[a][b][c][s] = v;
                    }
        if (tig == 0) {
#pragma unroll
            for (int mt = 0; mt < 2; mt++)
#pragma unroll
                for (int rh = 0; rh < 2; rh++) {
                    int r = row0 + wm * 32 + mt * 16 + gid + rh * 8;
                    if (r < NN) {
#pragma unroll
                        for (int hh = 0; hh < 2; hh++) {
                            int head = wn * 2 + hh;
                            g_ssrc[r * 4 + head] = sc[mt][rh][hh][0];
                            g_sdst[r * 4 + head] = sc[mt][rh][hh][1];
                        }
                    }
                }
        }
    }
}

// ---------------- CSR build ----------------
__global__ void k_cnt_zero() {
    int i = blockIdx.x * blockDim.x + threadIdx.x;
    if (i < NN) g_cnt[i] = 0;
}
__global__ void k_deg(const int* __restrict__ ei) {
    int e = blockIdx.x * blockDim.x + threadIdx.x;
    if (e < NE) atomicAdd(&g_cnt[ei[NE + e]], 1);
}
__global__ void k_scan1() {
    __shared__ int wsum[8];
    int b = blockIdx.x, t = threadIdx.x;
    int idx0 = b * 1024 + t * 4;
    int v[4];
#pragma unroll
    for (int k = 0; k < 4; k++) v[k] = (idx0 + k < NN) ? g_cnt[idx0 + k] : 0;
    int s = v[0] + v[1] + v[2] + v[3];
    int lane = t & 31, wid = t >> 5;
    int incl = s;
#pragma unroll
    for (int off = 1; off <= 16; off <<= 1) {
        int nv = __shfl_up_sync(0xffffffffu, incl, off);
        if (lane >= off) incl += nv;
    }
    if (lane == 31) wsum[wid] = incl;
    __syncthreads();
    if (t == 0) {
        int r = 0;
#pragma unroll
        for (int w = 0; w < 8; w++) { int x = wsum[w]; wsum[w] = r; r += x; }
    }
    __syncthreads();
    int excl = incl - s + wsum[wid];
    int run = excl;
#pragma unroll
    for (int k = 0; k < 4; k++) {
        if (idx0 + k < NN) g_off[idx0 + k] = run;
        run += v[k];
    }
    if (t == 255) g_bsum[b] = excl + s;
}
__global__ void k_scan2() {
    int r = 0;
    for (int b = 0; b < SCAN_B; b++) { g_boff[b] = r; r += g_bsum[b]; }
    g_off[NN] = r;
}
__global__ void k_scan3() {
    int i = blockIdx.x * blockDim.x + threadIdx.x;
    if (i >= NN) return;
    int o = g_off[i] + g_boff[i >> 10];
    g_off[i] = o;
    g_cursor[i] = o;
}
__global__ void k_fill(const int* __restrict__ ei) {
    int e = blockIdx.x * blockDim.x + threadIdx.x;
    if (e >= NE) return;
    int dst = ei[NE + e];
    int pos = atomicAdd(&g_cursor[dst], 1);
    g_csr[pos] = ei[e];
}

// ---------------- per-head global max of scores ----------------
__global__ void k_shift_init() {
    if (threadIdx.x < NHEAD) {
        g_maxs[threadIdx.x] = __int_as_float(0xff800000u);
        g_maxd[threadIdx.x] = __int_as_float(0xff800000u);
    }
}
__global__ void k_shift() {
    int i0 = blockIdx.x * blockDim.x + threadIdx.x;
    int stride = gridDim.x * blockDim.x;
    float ms = __int_as_float(0xff800000u);
    float md = ms;
    for (int i = i0; i < NN * NHEAD; i += stride) {
        ms = fmaxf(ms, g_ssrc[i]);
        md = fmaxf(md, g_sdst[i]);
    }
#pragma unroll
    for (int off = 4; off <= 16; off <<= 1) {
        ms = fmaxf(ms, __shfl_xor_sync(0xffffffffu, ms, off));
        md = fmaxf(md, __shfl_xor_sync(0xffffffffu, md, off));
    }
    int lane = threadIdx.x & 31;
    if (lane < 4) {
        atomicMaxF(&g_maxs[lane], ms);
        atomicMaxF(&g_maxd[lane], md);
    }
}

// ---------------- fused GAT aggregate (warp per dst) ----------------
__global__ void k_gat(const float* __restrict__ bias) {
    int n = (blockIdx.x * blockDim.x + threadIdx.x) >> 5;
    if (n >= NN) return;
    int lane = threadIdx.x & 31;
    int head = lane >> 3;

    float shift = lrelu(g_maxs[head] + g_maxd[head]);
    float sd = g_sdst[n * 4 + head];

    float p = __expf(lrelu(g_ssrc[n * 4 + head] + sd) - shift);
    float4 hv = ((const float4*)g_bufH)[n * 32 + lane];
    float ax = hv.x * p, ay = hv.y * p, az = hv.z * p, aw = hv.w * p;
    float den = p;

    int o0 = g_off[n], o1 = g_off[n + 1];
    for (int base = o0; base < o1; base += 32) {
        int id = 0;
        if (base + lane < o1) id = g_csr[base + lane];
        int cnt = min(32, o1 - base);
#pragma unroll 4
        for (int j = 0; j < cnt; j++) {
            int src = __shfl_sync(0xffffffffu, id, j);
            float ss = g_ssrc[src * 4 + head];
            float pe = __expf(lrelu(ss + sd) - shift);
            float4 h = ((const float4*)g_bufH)[src * 32 + lane];
            ax += h.x * pe; ay += h.y * pe; az += h.z * pe; aw += h.w * pe;
            den += pe;
        }
    }
    float inv = 1.f / den;
    float4 b = ((const float4*)bias)[lane];
    float4 o;
    o.x = eluf(ax * inv + b.x);
    o.y = eluf(ay * inv + b.y);
    o.z = eluf(az * inv + b.z);
    o.w = eluf(aw * inv + b.w);
    ((float4*)g_bufX)[n * 32 + lane] = o;
}

// ---------------- graph segment offsets ----------------
__global__ void k_start_init() {
    int g = threadIdx.x;
    if (g <= NG) g_start[g] = NN;
}
__global__ void k_start_fill(const int* __restrict__ batch) {
    int i = blockIdx.x * blockDim.x + threadIdx.x;
    if (i >= NN) return;
    int b = batch[i];
    int bp = (i == 0) ? -1 : batch[i - 1];
    for (int g = bp + 1; g <= b; ++g) g_start[g] = i;
}

// ---------------- GraphNorm stats ----------------
__global__ void k_norm_stats(const float* __restrict__ nms) {
    __shared__ float sh[256], sh2[256];
    int g = blockIdx.x, q = blockIdx.y;
    int tc = threadIdx.x & 31, tr = threadIdx.x >> 5;
    int c = q * 32 + tc;
    int s0 = g_start[g], s1 = g_start[g + 1];
    float s = 0.f, s2 = 0.f;
    for (int r = s0 + tr; r < s1; r += 8) {
        float v = g_bufX[r * CATC + c];
        s += v; s2 += v * v;
    }
    sh[threadIdx.x] = s; sh2[threadIdx.x] = s2;
    __syncthreads();
    for (int off = 128; off >= 32; off >>= 1) {
        if (threadIdx.x < off) {
            sh[threadIdx.x] += sh[threadIdx.x + off];
            sh2[threadIdx.x] += sh2[threadIdx.x + off];
        }
        __syncthreads();
    }
    if (threadIdx.x < 32) {
        int cnt = s1 - s0;
        float mean = 0.f, inv = 0.f;
        if (cnt > 0) {
            float fc = (float)cnt;
            mean = sh[tc] / fc;
            float ms = nms[c];
            float var = sh2[tc] / fc - (2.f * ms - ms * ms) * mean * mean;
            inv = rsqrtf(var + EPSN);
        }
        g_mean[g * CATC + c] = mean;
        g_inv[g * CATC + c] = inv;
    }
}

__global__ void k_norm_apply(const int* __restrict__ batch,
                             const float* __restrict__ w, const float* __restrict__ b,
                             const float* __restrict__ nms) {
    int i = blockIdx.x * blockDim.x + threadIdx.x;
    if (i >= NN * 32) return;
    int n = i >> 5, c4 = i & 31;
    int g = batch[n];
    float4 v  = ((const float4*)g_bufX)[i];
    float4 mn = ((const float4*)g_mean)[g * 32 + c4];
    float4 iv = ((const float4*)g_inv)[g * 32 + c4];
    float4 wv = ((const float4*)w)[c4];
    float4 bv = ((const float4*)b)[c4];
    float4 mv = ((const float4*)nms)[c4];
    v.x = wv.x * (v.x - mv.x * mn.x) * iv.x + bv.x;
    v.y = wv.y * (v.y - mv.y * mn.y) * iv.y + bv.y;
    v.z = wv.z * (v.z - mv.z * mn.z) * iv.z + bv.z;
    v.w = wv.w * (v.w - mv.w * mn.w) * iv.w + bv.w;
    ((float4*)g_bufX)[i] = v;
}

// ---------------- global max pool ----------------
__global__ void k_pool() {
    __shared__ float sh[256];
    int g = blockIdx.x, q = blockIdx.y;
    int tc = threadIdx.x & 31, tr = threadIdx.x >> 5;
    int c = q * 32 + tc;
    int s0 = g_start[g], s1 = g_start[g + 1];
    float m = __int_as_float(0xff800000u);
    for (int r = s0 + tr; r < s1; r += 8)
        m = fmaxf(m, g_bufX[r * CATC + c]);
    sh[threadIdx.x] = m;
    __syncthreads();
    for (int off = 128; off >= 32; off >>= 1) {
        if (threadIdx.x < off) sh[threadIdx.x] = fmaxf(sh[threadIdx.x], sh[threadIdx.x + off]);
        __syncthreads();
    }
    if (threadIdx.x < 32) g_pool[g * CATC + c] = sh[tc];
}

// ---------------- final fc ----------------
__global__ void k_fc(const float* __restrict__ fw, const float* __restrict__ fb,
                     float* __restrict__ out) {
    int g = blockIdx.x, o = threadIdx.x;
    float acc = fb[o];
#pragma unroll
    for (int c = 0; c < CATC; c += 4) {
        float4 p  = *(const float4*)&g_pool[g * CATC + c];
        float4 wv = *(const float4*)&fw[o * CATC + c];
        acc += p.x * wv.x + p.y * wv.y + p.z * wv.z + p.w * wv.w;
    }
    out[g * OUTD + o] = acc;
}

// ---------------- launch ----------------
extern "C" void kernel_launch(void* const* d_in, const int* in_sizes, int n_in,
                              void* d_out, int out_size) {
    const float* x     = (const float*)d_in[0];
    const int*   ei    = (const int*)d_in[1];
    const int*   batch = (const int*)d_in[2];
    const float* enc_w = (const float*)d_in[3];
    const float* enc_b = (const float*)d_in[4];
    const float* w1    = (const float*)d_in[5];
    const float* as1   = (const float*)d_in[6];
    const float* ad1   = (const float*)d_in[7];
    const float* b1    = (const float*)d_in[8];
    const float* n1w   = (const float*)d_in[9];
    const float* n1b   = (const float*)d_in[10];
    const float* n1ms  = (const float*)d_in[11];
    const float* w2    = (const float*)d_in[12];
    const float* as2   = (const float*)d_in[13];
    const float* ad2   = (const float*)d_in[14];
    const float* b2    = (const float*)d_in[15];
    const float* n2w   = (const float*)d_in[16];
    const float* n2b   = (const float*)d_in[17];
    const float* n2ms  = (const float*)d_in[18];
    const float* fw    = (const float*)d_in[19];
    const float* fb    = (const float*)d_in[20];
    float* out = (float*)d_out;

    cudaFuncSetAttribute(k_tgemm<0, 0, true, false>,
                         cudaFuncAttributeMaxDynamicSharedMemorySize, TG_SMEM);
    cudaFuncSetAttribute(k_tgemm<1, 1, false, true>,
                         cudaFuncAttributeMaxDynamicSharedMemorySize, TG_SMEM);

    const int gemmBlocks = (NN + 127) / 128;
    const int elemBlocks = (NN * 32 + 255) / 256;
    const int gatBlocks  = (NN * 32 + 255) / 256;
    const int edgeBlocks = (NE + 255) / 256;

    k_start_init<<<1, NG + 1>>>();
    k_start_fill<<<(NN + 255) / 256, 256>>>(batch);
    k_cnt_zero<<<(NN + 255) / 256, 256>>>();
    k_deg<<<edgeBlocks, 256>>>(ei);
    k_scan1<<<SCAN_B, 256>>>();
    k_scan2<<<1, 1>>>();
    k_scan3<<<(NN + 255) / 256, 256>>>();
    k_fill<<<edgeBlocks, 256>>>(ei);

    // encoder
    k_wconv<<<32, 256>>>(enc_w);
    k_tgemm<0, 0, true, false><<<gemmBlocks, 256, TG_SMEM>>>(x, enc_b, nullptr, nullptr);

    // ---- layer 1 ----
    k_wconv<<<32, 256>>>(w1);
    k_tgemm<1, 1, false, true><<<gemmBlocks, 256, TG_SMEM>>>(nullptr, nullptr, as1, ad1);
    k_shift_init<<<1, 32>>>();
    k_shift<<<296, 256>>>();
    k_gat<<<gatBlocks, 256>>>(b1);
    k_norm_stats<<<dim3(NG, 4), 256>>>(n1ms);
    k_norm_apply<<<elemBlocks, 256>>>(batch, n1w, n1b, n1ms);

    // ---- layer 2 ----
    k_wconv<<<32, 256>>>(w2);
    k_tgemm<1, 1, false, true><<<gemmBlocks, 256, TG_SMEM>>>(nullptr, nullptr, as2, ad2);
    k_shift_init<<<1, 32>>>();
    k_shift<<<296, 256>>>();
    k_gat<<<gatBlocks, 256>>>(b2);
    k_norm_stats<<<dim3(NG, 4), 256>>>(n2ms);
    k_norm_apply<<<elemBlocks, 256>>>(batch, n2w, n2b, n2ms);

    // ---- pool + fc ----
    k_pool<<<dim3(NG, 4), 256>>>();
    k_fc<<<NG, OUTD>>>(fw, fb, out);
}

// round 8
// speedup vs baseline: 1.7783x; 1.1055x over previous
#include <cuda_runtime.h>
#include <cuda_fp16.h>
#include <math.h>
#include <stdint.h>

#define NN    100000
#define NE    1600000
#define NG    64
#define CATC  128
#define NHEAD 4
#define OUTD  64
#define EPSN  1e-5f
#define SLOPE 0.2f
#define SCAN_B ((NN + 1023) / 1024)   // 98

// ---------------- scratch (device globals) ----------------
__device__ float  g_bufX[NN * CATC];
__device__ float  g_bufH[NN * CATC];
__device__ __half2 g_bufH16[NN * 64];
__device__ float  g_ssrc[NN * NHEAD];
__device__ float  g_sdst[NN * NHEAD];
__device__ float  g_maxs[NHEAD];
__device__ float  g_maxd[NHEAD];
__device__ float  g_nA[NG * CATC];
__device__ float  g_nB[NG * CATC];
__device__ float  g_pool[NG * CATC];
__device__ int    g_start[NG + 2];
__device__ int    g_cnt[NN];
__device__ int    g_off[NN + 1];
__device__ int    g_cursor[NN];
__device__ int    g_bsum[SCAN_B];
__device__ int    g_boff[SCAN_B];
__device__ int    g_csr[NE];
__device__ uint4  g_wfrag[3 * 16 * 16 * 32];  // [layer][ntG][ktG][lane]

__device__ __forceinline__ float lrelu(float x) { return x > 0.f ? x : SLOPE * x; }
__device__ __forceinline__ float eluf(float x)  { return x > 0.f ? x : __expf(x) - 1.f; }

__device__ __forceinline__ void atomicMaxF(float* a, float v) {
    if (v >= 0.f) atomicMax((int*)a, __float_as_int(v));
    else          atomicMin((unsigned int*)a, __float_as_uint(v));
}

__device__ __forceinline__ uint32_t tf32rn(float x) {
    uint32_t r;
    asm("cvt.rna.tf32.f32 %0, %1;" : "=r"(r) : "f"(x));
    return r;
}
__device__ __forceinline__ void mma8(float* d, uint32_t a0, uint32_t a1,
                                     uint32_t a2, uint32_t a3,
                                     uint32_t b0, uint32_t b1) {
    asm volatile(
        "mma.sync.aligned.m16n8k8.row.col.f32.tf32.tf32.f32 "
        "{%0,%1,%2,%3}, {%4,%5,%6,%7}, {%8,%9}, {%0,%1,%2,%3};"
        : "+f"(d[0]), "+f"(d[1]), "+f"(d[2]), "+f"(d[3])
        : "r"(a0), "r"(a1), "r"(a2), "r"(a3), "r"(b0), "r"(b1));
}

// ---------------- all W -> fragments (once) ----------------
__global__ void k_wconv3(const float* __restrict__ w0,
                         const float* __restrict__ w1,
                         const float* __restrict__ w2) {
    int idx = blockIdx.x * blockDim.x + threadIdx.x;   // 0..24575
    if (idx >= 3 * 8192) return;
    int l = idx >> 13, s = idx & 8191;
    const float* W = (l == 0) ? w0 : (l == 1) ? w1 : w2;
    int lane = s & 31, ktG = (s >> 5) & 15, ntG = s >> 9;
    int n = ntG * 8 + (lane >> 2);
    int k0 = ktG * 8 + (lane & 3);
    float v0 = W[n * CATC + k0];
    float v1 = W[n * CATC + k0 + 4];
    uint4 f;
    f.x = tf32rn(v0);
    f.y = tf32rn(v1);
    f.z = tf32rn(v0 - __uint_as_float(f.x));
    f.w = tf32rn(v1 - __uint_as_float(f.y));
    g_wfrag[idx] = f;
}

// ---------------- TF32 tensor GEMM (+bias)(+scores)(+fused input norm) ---------
#define TG_SMEM ((128 * 132 + 384) * 4)

template <int ASEL, int DSEL, int WSEL, bool BIAS, bool SCORES, bool NORM>
__global__ void __launch_bounds__(256, 2)
k_tgemm(const float* __restrict__ Aext,
        const float* __restrict__ bias,
        const float* __restrict__ a_src,
        const float* __restrict__ a_dst,
        const int* __restrict__ batch) {
    extern __shared__ float sm[];
    float* aT   = sm;                  // [128][132]
    float* sBia = sm + 128 * 132;
    float* sSrc = sBia + 128;
    float* sDst = sSrc + 128;

    const float* A = (ASEL == 0) ? Aext : g_bufX;
    float* O       = (DSEL == 0) ? g_bufX : g_bufH;

    int tid = threadIdx.x, wid = tid >> 5, lane = tid & 31;
    int wm = wid >> 1, wn = wid & 1, gid = lane >> 2, tig = lane & 3;
    int row0 = blockIdx.x * 128;

    if (tid < 128) {
        if (BIAS) sBia[tid] = bias[tid];
        if (SCORES) { sSrc[tid] = a_src[tid]; sDst[tid] = a_dst[tid]; }
    }

    // stage A tile (raw or norm-affine applied), padded stride 132
#pragma unroll
    for (int i = 0; i < 16; i++) {
        int idx = tid + 256 * i;       // 0..4095
        int r = idx >> 5, q = idx & 31;
        int grow = row0 + r;
        float4 v = make_float4(0.f, 0.f, 0.f, 0.f);
        if (grow < NN) {
            v = ((const float4*)A)[grow * 32 + q];
            if (NORM) {
                int g = batch[grow];
                float4 a4 = ((const float4*)g_nA)[g * 32 + q];
                float4 b4 = ((const float4*)g_nB)[g * 32 + q];
                v.x = fmaf(v.x, a4.x, b4.x);
                v.y = fmaf(v.y, a4.y, b4.y);
                v.z = fmaf(v.z, a4.z, b4.z);
                v.w = fmaf(v.w, a4.w, b4.w);
            }
        }
        *(float4*)&aT[r * 132 + q * 4] = v;
    }
    __syncthreads();

    float d[2][8][4];
#pragma unroll
    for (int mt = 0; mt < 2; mt++)
#pragma unroll
        for (int nt = 0; nt < 8; nt++)
#pragma unroll
            for (int f = 0; f < 4; f++) d[mt][nt][f] = 0.f;

    const uint4* wf = g_wfrag + WSEL * 8192;

#pragma unroll 4
    for (int ktG = 0; ktG < 16; ktG++) {
        uint4 bb[8];
#pragma unroll
        for (int nt = 0; nt < 8; nt++)
            bb[nt] = wf[(((wn * 8 + nt) << 4) + ktG) * 32 + lane];
        uint32_t aH[2][4], aL[2][4];
#pragma unroll
        for (int mt = 0; mt < 2; mt++) {
            int rb = wm * 32 + mt * 16 + gid;
            int c = ktG * 8 + tig;
            float v0 = aT[rb * 132 + c];
            float v1 = aT[(rb + 8) * 132 + c];
            float v2 = aT[rb * 132 + c + 4];
            float v3 = aT[(rb + 8) * 132 + c + 4];
            aH[mt][0] = tf32rn(v0); aL[mt][0] = tf32rn(v0 - __uint_as_float(aH[mt][0]));
            aH[mt][1] = tf32rn(v1); aL[mt][1] = tf32rn(v1 - __uint_as_float(aH[mt][1]));
            aH[mt][2] = tf32rn(v2); aL[mt][2] = tf32rn(v2 - __uint_as_float(aH[mt][2]));
            aH[mt][3] = tf32rn(v3); aL[mt][3] = tf32rn(v3 - __uint_as_float(aH[mt][3]));
        }
#pragma unroll
        for (int nt = 0; nt < 8; nt++)
#pragma unroll
            for (int mt = 0; mt < 2; mt++) {
                mma8(d[mt][nt], aH[mt][0], aH[mt][1], aH[mt][2], aH[mt][3], bb[nt].x, bb[nt].y);
                mma8(d[mt][nt], aH[mt][0], aH[mt][1], aH[mt][2], aH[mt][3], bb[nt].z, bb[nt].w);
                mma8(d[mt][nt], aL[mt][0], aL[mt][1], aL[mt][2], aL[mt][3], bb[nt].x, bb[nt].y);
            }
    }

    // epilogue: store (+half copy) + fused scores
    float sc[2][2][2][2];
    if (SCORES) {
#pragma unroll
        for (int a = 0; a < 2; a++)
#pragma unroll
            for (int b = 0; b < 2; b++)
#pragma unroll
                for (int c = 0; c < 2; c++) {
                    sc[a][b][c][0] = 0.f; sc[a][b][c][1] = 0.f;
                }
    }
#pragma unroll
    for (int mt = 0; mt < 2; mt++) {
        int r0 = row0 + wm * 32 + mt * 16 + gid;
#pragma unroll
        for (int nt = 0; nt < 8; nt++) {
            int c0 = wn * 64 + nt * 8 + 2 * tig;
            float v0 = d[mt][nt][0], v1 = d[mt][nt][1];
            float v2 = d[mt][nt][2], v3 = d[mt][nt][3];
            if (SCORES) {
                int hh = nt >> 2;
                float s0 = sSrc[c0], s1 = sSrc[c0 + 1];
                float t0 = sDst[c0], t1 = sDst[c0 + 1];
                sc[mt][0][hh][0] += v0 * s0 + v1 * s1;
                sc[mt][0][hh][1] += v0 * t0 + v1 * t1;
                sc[mt][1][hh][0] += v2 * s0 + v3 * s1;
                sc[mt][1][hh][1] += v2 * t0 + v3 * t1;
            }
            if (BIAS) {
                float b0 = sBia[c0], b1 = sBia[c0 + 1];
                v0 += b0; v1 += b1; v2 += b0; v3 += b1;
            }
            if (r0 < NN) {
                *(float2*)&O[r0 * CATC + c0] = make_float2(v0, v1);
                if (DSEL == 1) g_bufH16[r0 * 64 + (c0 >> 1)] = __floats2half2_rn(v0, v1);
            }
            if (r0 + 8 < NN) {
                *(float2*)&O[(r0 + 8) * CATC + c0] = make_float2(v2, v3);
                if (DSEL == 1) g_bufH16[(r0 + 8) * 64 + (c0 >> 1)] = __floats2half2_rn(v2, v3);
            }
        }
    }
    if (SCORES) {
#pragma unroll
        for (int a = 0; a < 2; a++)
#pragma unroll
            for (int b = 0; b < 2; b++)
#pragma unroll
                for (int c = 0; c < 2; c++)
#pragma unroll
                    for (int s = 0; s < 2; s++) {
                        float v = sc[a][b][c][s];
                        v += __shfl_xor_sync(0xffffffffu, v, 1);
                        v += __shfl_xor_sync(0xffffffffu, v, 2);
                        sc[a][b][c][s] = v;
                    }
        if (tig == 0) {
#pragma unroll
            for (int mt = 0; mt < 2; mt++)
#pragma unroll
                for (int rh = 0; rh < 2; rh++) {
                    int r = row0 + wm * 32 + mt * 16 + gid + rh * 8;
                    if (r < NN) {
#pragma unroll
                        for (int hh = 0; hh < 2; hh++) {
                            int head = wn * 2 + hh;
                            g_ssrc[r * 4 + head] = sc[mt][rh][hh][0];
                            g_sdst[r * 4 + head] = sc[mt][rh][hh][1];
                        }
                    }
                }
        }
    }
}

// ---------------- pre: zero counts + preset g_start ----------------
__global__ void k_pre() {
    int i = blockIdx.x * blockDim.x + threadIdx.x;
    if (i < NN) g_cnt[i] = 0;
    if (i <= NG) g_start[i] = NN;
    if (i < NHEAD) {
        g_maxs[i] = __int_as_float(0xff800000u);
        g_maxd[i] = __int_as_float(0xff800000u);
    }
}
__global__ void k_start_fill(const int* __restrict__ batch) {
    int i = blockIdx.x * blockDim.x + threadIdx.x;
    if (i >= NN) return;
    int b = batch[i];
    int bp = (i == 0) ? -1 : batch[i - 1];
    for (int g = bp + 1; g <= b; ++g) g_start[g] = i;
}
__global__ void k_deg(const int* __restrict__ ei) {
    int e = blockIdx.x * blockDim.x + threadIdx.x;
    if (e < NE) atomicAdd(&g_cnt[ei[NE + e]], 1);
}
__global__ void k_scan1() {
    __shared__ int wsum[8];
    int b = blockIdx.x, t = threadIdx.x;
    int idx0 = b * 1024 + t * 4;
    int v[4];
#pragma unroll
    for (int k = 0; k < 4; k++) v[k] = (idx0 + k < NN) ? g_cnt[idx0 + k] : 0;
    int s = v[0] + v[1] + v[2] + v[3];
    int lane = t & 31, wid = t >> 5;
    int incl = s;
#pragma unroll
    for (int off = 1; off <= 16; off <<= 1) {
        int nv = __shfl_up_sync(0xffffffffu, incl, off);
        if (lane >= off) incl += nv;
    }
    if (lane == 31) wsum[wid] = incl;
    __syncthreads();
    if (t == 0) {
        int r = 0;
#pragma unroll
        for (int w = 0; w < 8; w++) { int x = wsum[w]; wsum[w] = r; r += x; }
    }
    __syncthreads();
    int excl = incl - s + wsum[wid];
    int run = excl;
#pragma unroll
    for (int k = 0; k < 4; k++) {
        if (idx0 + k < NN) g_off[idx0 + k] = run;
        run += v[k];
    }
    if (t == 255) g_bsum[b] = excl + s;
}
__global__ void k_scan2() {
    int r = 0;
    for (int b = 0; b < SCAN_B; b++) { g_boff[b] = r; r += g_bsum[b]; }
    g_off[NN] = r;
}
__global__ void k_scan3() {
    int i = blockIdx.x * blockDim.x + threadIdx.x;
    if (i >= NN) return;
    int o = g_off[i] + g_boff[i >> 10];
    g_off[i] = o;
    g_cursor[i] = o;
}
__global__ void k_fill(const int* __restrict__ ei) {
    int e = blockIdx.x * blockDim.x + threadIdx.x;
    if (e >= NE) return;
    int dst = ei[NE + e];
    int pos = atomicAdd(&g_cursor[dst], 1);
    g_csr[pos] = ei[e];
}

// ---------------- per-head global max of scores ----------------
__global__ void k_shift_init() {
    if (threadIdx.x < NHEAD) {
        g_maxs[threadIdx.x] = __int_as_float(0xff800000u);
        g_maxd[threadIdx.x] = __int_as_float(0xff800000u);
    }
}
__global__ void k_shift() {
    int i0 = blockIdx.x * blockDim.x + threadIdx.x;
    int stride = gridDim.x * blockDim.x;
    float ms = __int_as_float(0xff800000u);
    float md = ms;
    for (int i = i0; i < NN * NHEAD; i += stride) {
        ms = fmaxf(ms, g_ssrc[i]);
        md = fmaxf(md, g_sdst[i]);
    }
#pragma unroll
    for (int off = 4; off <= 16; off <<= 1) {
        ms = fmaxf(ms, __shfl_xor_sync(0xffffffffu, ms, off));
        md = fmaxf(md, __shfl_xor_sync(0xffffffffu, md, off));
    }
    int lane = threadIdx.x & 31;
    if (lane < 4) {
        atomicMaxF(&g_maxs[lane], ms);
        atomicMaxF(&g_maxd[lane], md);
    }
}

// ---------------- fused GAT aggregate (warp per dst, fp16 neighbor gather) -------
__global__ void k_gat(const float* __restrict__ bias) {
    int n = (blockIdx.x * blockDim.x + threadIdx.x) >> 5;
    if (n >= NN) return;
    int lane = threadIdx.x & 31;
    int head = lane >> 3;

    float shift = lrelu(g_maxs[head] + g_maxd[head]);
    float sd = g_sdst[n * 4 + head];

    // self-loop in fp32
    float p = __expf(lrelu(g_ssrc[n * 4 + head] + sd) - shift);
    float4 hv = ((const float4*)g_bufH)[n * 32 + lane];
    float ax = hv.x * p, ay = hv.y * p, az = hv.z * p, aw = hv.w * p;
    float den = p;

    int o0 = g_off[n], o1 = g_off[n + 1];
    for (int base = o0; base < o1; base += 32) {
        int id = 0;
        if (base + lane < o1) id = g_csr[base + lane];
        int cnt = min(32, o1 - base);
#pragma unroll 4
        for (int j = 0; j < cnt; j++) {
            int src = __shfl_sync(0xffffffffu, id, j);
            float ss = g_ssrc[src * 4 + head];
            float pe = __expf(lrelu(ss + sd) - shift);
            uint2 hraw = ((const uint2*)g_bufH16)[src * 32 + lane];
            float2 f01 = __half22float2(*(__half2*)&hraw.x);
            float2 f23 = __half22float2(*(__half2*)&hraw.y);
            ax += f01.x * pe; ay += f01.y * pe;
            az += f23.x * pe; aw += f23.y * pe;
            den += pe;
        }
    }
    float inv = 1.f / den;
    float4 b = ((const float4*)bias)[lane];
    float4 o;
    o.x = eluf(ax * inv + b.x);
    o.y = eluf(ay * inv + b.y);
    o.z = eluf(az * inv + b.z);
    o.w = eluf(aw * inv + b.w);
    ((float4*)g_bufX)[n * 32 + lane] = o;
}

// ---------------- GraphNorm stats -> affine A',B' ----------------
__global__ void k_norm_stats(const float* __restrict__ nw,
                             const float* __restrict__ nb,
                             const float* __restrict__ nms) {
    __shared__ float sh[256], sh2[256];
    int g = blockIdx.x, q = blockIdx.y;
    int tc = threadIdx.x & 31, tr = threadIdx.x >> 5;
    int c = q * 32 + tc;
    int s0 = g_start[g], s1 = g_start[g + 1];
    float s = 0.f, s2 = 0.f;
    for (int r = s0 + tr; r < s1; r += 8) {
        float v = g_bufX[r * CATC + c];
        s += v; s2 += v * v;
    }
    sh[threadIdx.x] = s; sh2[threadIdx.x] = s2;
    __syncthreads();
    for (int off = 128; off >= 32; off >>= 1) {
        if (threadIdx.x < off) {
            sh[threadIdx.x] += sh[threadIdx.x + off];
            sh2[threadIdx.x] += sh2[threadIdx.x + off];
        }
        __syncthreads();
    }
    if (threadIdx.x < 32) {
        int cnt = s1 - s0;
        float A = 0.f, B = nb[c];
        if (cnt > 0) {
            float fc = (float)cnt;
            float mean = sh[tc] / fc;
            float ms = nms[c];
            float var = sh2[tc] / fc - (2.f * ms - ms * ms) * mean * mean;
            float inv = rsqrtf(var + EPSN);
            A = nw[c] * inv;
            B = nb[c] - A * ms * mean;
        }
        g_nA[g * CATC + c] = A;
        g_nB[g * CATC + c] = B;
    }
}

// ---------------- global max pool (+fused norm2 affine) ----------------
__global__ void k_pool() {
    __shared__ float sh[256];
    int g = blockIdx.x, q = blockIdx.y;
    int tc = threadIdx.x & 31, tr = threadIdx.x >> 5;
    int c = q * 32 + tc;
    int s0 = g_start[g], s1 = g_start[g + 1];
    float a = g_nA[g * CATC + c], b = g_nB[g * CATC + c];
    float m = __int_as_float(0xff800000u);
    for (int r = s0 + tr; r < s1; r += 8)
        m = fmaxf(m, fmaf(g_bufX[r * CATC + c], a, b));
    sh[threadIdx.x] = m;
    __syncthreads();
    for (int off = 128; off >= 32; off >>= 1) {
        if (threadIdx.x < off) sh[threadIdx.x] = fmaxf(sh[threadIdx.x], sh[threadIdx.x + off]);
        __syncthreads();
    }
    if (threadIdx.x < 32) g_pool[g * CATC + c] = sh[tc];
}

// ---------------- final fc ----------------
__global__ void k_fc(const float* __restrict__ fw, const float* __restrict__ fb,
                     float* __restrict__ out) {
    int g = blockIdx.x, o = threadIdx.x;
    float acc = fb[o];
#pragma unroll
    for (int c = 0; c < CATC; c += 4) {
        float4 p  = *(const float4*)&g_pool[g * CATC + c];
        float4 wv = *(const float4*)&fw[o * CATC + c];
        acc += p.x * wv.x + p.y * wv.y + p.z * wv.z + p.w * wv.w;
    }
    out[g * OUTD + o] = acc;
}

// ---------------- launch ----------------
extern "C" void kernel_launch(void* const* d_in, const int* in_sizes, int n_in,
                              void* d_out, int out_size) {
    const float* x     = (const float*)d_in[0];
    const int*   ei    = (const int*)d_in[1];
    const int*   batch = (const int*)d_in[2];
    const float* enc_w = (const float*)d_in[3];
    const float* enc_b = (const float*)d_in[4];
    const float* w1    = (const float*)d_in[5];
    const float* as1   = (const float*)d_in[6];
    const float* ad1   = (const float*)d_in[7];
    const float* b1    = (const float*)d_in[8];
    const float* n1w   = (const float*)d_in[9];
    const float* n1b   = (const float*)d_in[10];
    const float* n1ms  = (const float*)d_in[11];
    const float* w2    = (const float*)d_in[12];
    const float* as2   = (const float*)d_in[13];
    const float* ad2   = (const float*)d_in[14];
    const float* b2    = (const float*)d_in[15];
    const float* n2w   = (const float*)d_in[16];
    const float* n2b   = (const float*)d_in[17];
    const float* n2ms  = (const float*)d_in[18];
    const float* fw    = (const float*)d_in[19];
    const float* fb    = (const float*)d_in[20];
    float* out = (float*)d_out;

    cudaFuncSetAttribute(k_tgemm<0, 0, 0, true, false, false>,
                         cudaFuncAttributeMaxDynamicSharedMemorySize, TG_SMEM);
    cudaFuncSetAttribute(k_tgemm<1, 1, 1, false, true, false>,
                         cudaFuncAttributeMaxDynamicSharedMemorySize, TG_SMEM);
    cudaFuncSetAttribute(k_tgemm<1, 1, 2, false, true, true>,
                         cudaFuncAttributeMaxDynamicSharedMemorySize, TG_SMEM);

    const int gemmBlocks = (NN + 127) / 128;
    const int gatBlocks  = (NN * 32 + 255) / 256;
    const int edgeBlocks = (NE + 255) / 256;

    // prep + CSR build (shared by both layers)
    k_pre<<<(NN + 255) / 256, 256>>>();
    k_start_fill<<<(NN + 255) / 256, 256>>>(batch);
    k_wconv3<<<96, 256>>>(enc_w, w1, w2);
    k_deg<<<edgeBlocks, 256>>>(ei);
    k_scan1<<<SCAN_B, 256>>>();
    k_scan2<<<1, 1>>>();
    k_scan3<<<(NN + 255) / 256, 256>>>();
    k_fill<<<edgeBlocks, 256>>>(ei);

    // encoder
    k_tgemm<0, 0, 0, true, false, false><<<gemmBlocks, 256, TG_SMEM>>>(
        x, enc_b, nullptr, nullptr, nullptr);

    // ---- layer 1 ----
    k_tgemm<1, 1, 1, false, true, false><<<gemmBlocks, 256, TG_SMEM>>>(
        nullptr, nullptr, as1, ad1, nullptr);
    k_shift<<<296, 256>>>();
    k_gat<<<gatBlocks, 256>>>(b1);
    k_norm_stats<<<dim3(NG, 4), 256>>>(n1w, n1b, n1ms);

    // ---- layer 2 (A-staging applies norm1 affine) ----
    k_shift_init<<<1, 32>>>();
    k_tgemm<1, 1, 2, false, true, true><<<gemmBlocks, 256, TG_SMEM>>>(
        nullptr, nullptr, as2, ad2, batch);
    k_shift<<<296, 256>>>();
    k_gat<<<gatBlocks, 256>>>(b2);
    k_norm_stats<<<dim3(NG, 4), 256>>>(n2w, n2b, n2ms);

    // ---- pool (applies norm2 affine) + fc ----
    k_pool<<<dim3(NG, 4), 256>>>();
    k_fc<<<NG, OUTD>>>(fw, fb, out);
}